// round 15
// baseline (speedup 1.0000x reference)
#include <cuda_runtime.h>
#include <cuda_fp16.h>
#include <cstdint>

// ---------------------------------------------------------------------------
// QuantLinear, fp16 mma.sync path (base sm_103 target — tcgen05 unavailable).
//   out[8192,11008] = x[8192,4096] @ dequant(W)[4096,11008] + bias
// Pre-pass: x fp32 -> fp16 scratch, k-permuted within 8-groups to match the
// nibble-pair dequant order [v0,v4,v1,v5,v2,v6,v3,v7].
// Main: R14 skeleton (128x128x64 tile, 4 warps, 64x64 warp tiles, 2 CTA/SM)
// with DECOUPLED per-stage named barriers (FULL/EMPTY, arrive+sync count=256)
// replacing the per-tile __syncthreads, A ring deepened to 4 stages and B to
// 3 stages under an XOR-swizzled (SW128) layout, and 2-tile-ahead qweight
// register ping-pong. Warps may skew up to ~2 tiles, absorbing convoy jitter.
// ---------------------------------------------------------------------------

namespace {
constexpr int kInF  = 4096;
constexpr int kOutF = 11008;
constexpr int kM    = 8192;

constexpr int BM = 128;
constexpr int BN = 128;
constexpr int BK = 64;
constexpr int NT = kInF / BK;        // 64 k-tiles (even)

constexpr int STAGE = 128 * 128;     // 16384 B: swizzled tile (no padding)
constexpr int S_A   = 0;             // A: 4 stages
constexpr int S_B   = 4 * STAGE;     // B: 3 stages
constexpr int SMEM_TOTAL = 7 * STAGE;   // 114688 B = 112 KB (2 CTA/SM = 224 KB)
}  // namespace

// 67 MB fp16 scratch for converted x (static __device__: no runtime alloc)
__device__ __align__(128) __half g_x16[(size_t)kM * kInF];

// ---------------------------------------------------------------------------
__device__ __forceinline__ uint32_t smem_u32(const void* p) {
    uint32_t a;
    asm("{ .reg .u64 t; cvta.to.shared.u64 t, %1; cvt.u32.u64 %0, t; }"
        : "=r"(a) : "l"(p));
    return a;
}

#define LDSM_X4(r0, r1, r2, r3, addr)                                          \
    asm volatile("ldmatrix.sync.aligned.m8n8.x4.shared.b16 {%0,%1,%2,%3}, [%4];" \
                 : "=r"(r0), "=r"(r1), "=r"(r2), "=r"(r3) : "r"(addr))

#define MMA16816(d, a, b0, b1)                                                \
    asm volatile(                                                             \
        "mma.sync.aligned.m16n8k16.row.col.f32.f16.f16.f32 "                  \
        "{%0,%1,%2,%3}, {%4,%5,%6,%7}, {%8,%9}, {%0,%1,%2,%3};"               \
        : "+f"((d)[0]), "+f"((d)[1]), "+f"((d)[2]), "+f"((d)[3])              \
        : "r"((a)[0]), "r"((a)[1]), "r"((a)[2]), "r"((a)[3]),                 \
          "r"(b0), "r"(b1))

#define CP_ASYNC16(dst, src)                                                  \
    asm volatile("cp.async.cg.shared.global [%0], [%1], 16;"                  \
                 :: "r"(dst), "l"(src))
#define CP_COMMIT() asm volatile("cp.async.commit_group;")
#define CP_WAIT1()  asm volatile("cp.async.wait_group 1;")

// named barriers, 128 threads participating twice per phase (arrive + sync)
#define BARS(id)  asm volatile("bar.sync %0, 256;"   :: "r"(id) : "memory")
#define BARA(id)  asm volatile("bar.arrive %0, 256;" :: "r"(id) : "memory")
// ids: FULL(t) = t&3  (0..3), EMPTY(t) = 4 + (t&3)  (4..7)

// ---------------------------------------------------------------------------
// Pre-pass: x fp32 -> fp16, permuted within each 8-k group to
// [v0,v4,v1,v5,v2,v6,v3,v7] (matches nibble-pair dequant output order).
// ---------------------------------------------------------------------------
__global__ void __launch_bounds__(256)
convert_x_kernel(const float* __restrict__ x) {
    size_t i = (size_t)blockIdx.x * blockDim.x + threadIdx.x;  // one per 8 floats
    constexpr size_t TOT = (size_t)kM * kInF / 8;
    if (i >= TOT) return;
    const float4* s = reinterpret_cast<const float4*>(x) + i * 2;
    float4 a = s[0], b = s[1];
    __half2 h0 = __floats2half2_rn(a.x, b.x);   // (v0, v4)
    __half2 h1 = __floats2half2_rn(a.y, b.y);   // (v1, v5)
    __half2 h2 = __floats2half2_rn(a.z, b.z);   // (v2, v6)
    __half2 h3 = __floats2half2_rn(a.w, b.w);   // (v3, v7)
    uint4 o;
    o.x = *reinterpret_cast<uint32_t*>(&h0);
    o.y = *reinterpret_cast<uint32_t*>(&h1);
    o.z = *reinterpret_cast<uint32_t*>(&h2);
    o.w = *reinterpret_cast<uint32_t*>(&h3);
    reinterpret_cast<uint4*>(g_x16)[i] = o;
}

// ---------------------------------------------------------------------------
// Main GEMM kernel: 128 threads, 4 warps (2x2), 64x64 warp tiles
// ---------------------------------------------------------------------------
__global__ void __launch_bounds__(128, 2)
qlinear_hmma_kernel(const float* __restrict__ scales,
                    const float* __restrict__ bias,
                    const int*   __restrict__ qweight,
                    const int*   __restrict__ qzeros,
                    float*       __restrict__ out)
{
    extern __shared__ char smem[];
    const uint32_t sb = smem_u32(smem);
    const int tid  = threadIdx.x;
    const int lane = tid & 31;
    const int wid  = tid >> 5;               // 0..3
    const int warp_m = (wid & 1) * 64;
    const int warp_n = (wid >> 1) * 64;
    const int m0 = blockIdx.y * BM;
    const int n0 = blockIdx.x * BN;
    const int n  = n0 + tid;                 // this thread's B column
    const int zshift = (n & 7) * 4;
    const size_t zcol = (size_t)(n >> 3);

    // -------- A cp.async addressing (swizzled, per-thread constant) ---------
    const int a_r0 = tid >> 3;               // row 0..15 (+16j)
    const int a_c0 = tid & 7;                // chunk
    const __half* aP = g_x16 + (size_t)(m0 + a_r0) * kInF + a_c0 * 8;
    const uint32_t aDst = sb + S_A + a_r0 * 128 + (((a_c0 ^ (a_r0 & 7)) & 7) << 4);

    auto issue_a = [&](int t, int s) {
        const __half* src = aP + t * BK;
        const uint32_t dst = aDst + s * STAGE;
#pragma unroll
        for (int j = 0; j < 8; ++j)
            CP_ASYNC16(dst + j * 2048, src + (size_t)j * (16 * kInF));
    };

    // -------- qweight ping-pong (A = even tiles, B = odd tiles) -------------
    uint32_t QA[8], QB[8];
    __half2  hzA, hsA, hzB, hsB;
    const int* qP = qweight + n;

    auto ldg_qwA = [&](int t) {              // t even: fresh group consts
        const int* qpt = qP + (size_t)(t * 8) * kOutF;
#pragma unroll
        for (int i = 0; i < 8; ++i) QA[i] = (uint32_t)qpt[(size_t)i * kOutF];
        const int g = t >> 1;
        const float sc = scales[(size_t)g * kOutF + n];
        const int   z  = (qzeros[(size_t)g * (kOutF / 8) + zcol] >> zshift) & 15;
        const uint32_t zb = (0x6400u | (uint32_t)z) * 0x00010001u;
        hzA = *reinterpret_cast<const __half2*>(&zb);
        hsA = __float2half2_rn(sc);
    };
    auto ldg_qwB = [&](int t) {              // t odd: same group as t-1 (A buf)
        const int* qpt = qP + (size_t)(t * 8) * kOutF;
#pragma unroll
        for (int i = 0; i < 8; ++i) QB[i] = (uint32_t)qpt[(size_t)i * kOutF];
        hzB = hzA; hsB = hsA;
    };

    // -------- B dequant -> swizzled smem stage ------------------------------
    const int bsw7 = tid & 7;
    char* const bP = smem + S_B + tid * 128;
    auto sts_b = [&](int s, const uint32_t* qw, __half2 hz, __half2 hs) {
        char* bp = bP + s * STAGE;
#pragma unroll
        for (int i = 0; i < 8; ++i) {
            const uint32_t q = qw[i];
            uint32_t u0 = (q & 0x000F000Fu)         | 0x64006400u;
            uint32_t u1 = ((q >> 4) & 0x000F000Fu)  | 0x64006400u;
            uint32_t u2 = ((q >> 8) & 0x000F000Fu)  | 0x64006400u;
            uint32_t u3 = ((q >> 12) & 0x000F000Fu) | 0x64006400u;
            __half2 v0 = __hmul2(__hsub2(*reinterpret_cast<__half2*>(&u0), hz), hs);
            __half2 v1 = __hmul2(__hsub2(*reinterpret_cast<__half2*>(&u1), hz), hs);
            __half2 v2 = __hmul2(__hsub2(*reinterpret_cast<__half2*>(&u2), hz), hs);
            __half2 v3 = __hmul2(__hsub2(*reinterpret_cast<__half2*>(&u3), hz), hs);
            uint4 pk;
            pk.x = *reinterpret_cast<uint32_t*>(&v0);
            pk.y = *reinterpret_cast<uint32_t*>(&v1);
            pk.z = *reinterpret_cast<uint32_t*>(&v2);
            pk.w = *reinterpret_cast<uint32_t*>(&v3);
            *reinterpret_cast<uint4*>(bp + ((i ^ bsw7) << 4)) = pk;
        }
    };

    // -------- accumulators --------------------------------------------------
    float acc[4][8][4];
#pragma unroll
    for (int mt = 0; mt < 4; ++mt)
#pragma unroll
        for (int nt = 0; nt < 8; ++nt)
#pragma unroll
            for (int r = 0; r < 4; ++r) acc[mt][nt][r] = 0.f;

    // -------- ldmatrix addressing (swizzled) --------------------------------
    const int sw = lane & 7;                 // row&7 for both A and B patterns
    const uint32_t abase = sb + S_A + (warp_m + (lane & 15)) * 128;
    const uint32_t bbase = sb + S_B
                         + (warp_n + (lane & 7) + ((lane >> 4) << 3)) * 128;
    const int a_c = lane >> 4;               // A chunk base (0/1)
    const int b_c = (lane >> 3) & 1;         // B chunk base (0/1)
    uint32_t aoff[4], boff[4];
#pragma unroll
    for (int k16 = 0; k16 < 4; ++k16) {
        aoff[k16] = (uint32_t)(((a_c + 2 * k16) ^ sw) << 4);
        boff[k16] = (uint32_t)(((b_c + 2 * k16) ^ sw) << 4);
    }

    auto compute_tile = [&](int sA, int sB) {
        const uint32_t ab = abase + sA * STAGE;
        const uint32_t bb = bbase + sB * STAGE;
#pragma unroll
        for (int k16 = 0; k16 < 4; ++k16) {
            uint32_t af[4][4];
#pragma unroll
            for (int mt = 0; mt < 4; ++mt)
                LDSM_X4(af[mt][0], af[mt][1], af[mt][2], af[mt][3],
                        ab + mt * 2048 + aoff[k16]);
            uint32_t bf[4][4];
#pragma unroll
            for (int nt2 = 0; nt2 < 4; ++nt2)
                LDSM_X4(bf[nt2][0], bf[nt2][1], bf[nt2][2], bf[nt2][3],
                        bb + nt2 * 2048 + boff[k16]);
#pragma unroll
            for (int mt = 0; mt < 4; ++mt)
#pragma unroll
                for (int nt = 0; nt < 8; ++nt) {
                    const int h = (nt & 1) * 2;
                    MMA16816(acc[mt][nt], af[mt], bf[nt >> 1][h], bf[nt >> 1][h + 1]);
                }
        }
    };

    // -------- prologue ------------------------------------------------------
    issue_a(0, 0); CP_COMMIT();
    issue_a(1, 1); CP_COMMIT();
    ldg_qwA(0);
    ldg_qwB(1);
    sts_b(0, QA, hzA, hsA);                  // B(0) -> B stage 0
    CP_WAIT1();                              // own A(0) chunks landed
    BARA(0);                                 // arrive FULL(0)

    // -------- main loop: unrolled x2 (even/odd qw buffers) ------------------
    // iter t: [sync EMPTY(t-2)] [issue A(t+2)] [ldg qw(t+2)] [sts B(t+1)]
    //         [wait own A(t+1)] [arrive FULL(t+1)] [sync FULL(t)]
    //         [compute(t)] [arrive EMPTY(t)]
    int sB0 = 0;                             // t % 3
    for (int tt = 0; tt < NT; tt += 2) {
        // ---- even tile t = tt ----
        {
            const int t = tt;
            const int sB1 = (sB0 + 1 < 3) ? sB0 + 1 : 0;
            if (t >= 2) BARS(4 + ((t - 2) & 3));
            if (t + 2 < NT) issue_a(t + 2, (t + 2) & 3);
            CP_COMMIT();
            if (t + 2 < NT) ldg_qwA(t + 2);
            if (t + 1 < NT) sts_b(sB1, QB, hzB, hsB);
            CP_WAIT1();
            if (t + 1 < NT) BARA((t + 1) & 3);
            BARS(t & 3);
            compute_tile(t & 3, sB0);
            if (t + 2 < NT) BARA(4 + (t & 3));
            sB0 = sB1;
        }
        // ---- odd tile t = tt+1 ----
        {
            const int t = tt + 1;
            const int sB1 = (sB0 + 1 < 3) ? sB0 + 1 : 0;
            if (t >= 2) BARS(4 + ((t - 2) & 3));
            if (t + 2 < NT) issue_a(t + 2, (t + 2) & 3);
            CP_COMMIT();
            if (t + 2 < NT) ldg_qwB(t + 2);
            if (t + 1 < NT) sts_b(sB1, QA, hzA, hsA);
            CP_WAIT1();
            if (t + 1 < NT) BARA((t + 1) & 3);
            BARS(t & 3);
            compute_tile(t & 3, sB0);
            if (t + 2 < NT) BARA(4 + (t & 3));
            sB0 = sB1;
        }
    }

    // -------- epilogue: +bias, fp32 stores ---------------------------------
    const int g  = lane >> 2;
    const int tg = lane & 3;
#pragma unroll
    for (int nt = 0; nt < 8; ++nt) {
        const int c = n0 + warp_n + nt * 8 + tg * 2;
        const float2 bv = *reinterpret_cast<const float2*>(bias + c);
#pragma unroll
        for (int mt = 0; mt < 4; ++mt) {
            const int r0 = m0 + warp_m + mt * 16 + g;
            float2 v0 = make_float2(acc[mt][nt][0] + bv.x, acc[mt][nt][1] + bv.y);
            float2 v1 = make_float2(acc[mt][nt][2] + bv.x, acc[mt][nt][3] + bv.y);
            *reinterpret_cast<float2*>(out + (size_t)r0 * kOutF + c)       = v0;
            *reinterpret_cast<float2*>(out + (size_t)(r0 + 8) * kOutF + c) = v1;
        }
    }
}

// ---------------------------------------------------------------------------
extern "C" void kernel_launch(void* const* d_in, const int* in_sizes, int n_in,
                              void* d_out, int out_size)
{
    (void)in_sizes; (void)n_in; (void)out_size;
    const float* x       = (const float*)d_in[0];
    const float* scales  = (const float*)d_in[1];
    const float* bias    = (const float*)d_in[2];
    const int*   qweight = (const int*)d_in[3];
    const int*   qzeros  = (const int*)d_in[4];
    float*       out     = (float*)d_out;

    const size_t tot8 = (size_t)kM * kInF / 8;
    convert_x_kernel<<<(unsigned)((tot8 + 255) / 256), 256>>>(x);

    cudaFuncSetAttribute(qlinear_hmma_kernel,
                         cudaFuncAttributeMaxDynamicSharedMemorySize, SMEM_TOTAL);
    dim3 grid(kOutF / BN, kM / BM);  // (86, 64)
    qlinear_hmma_kernel<<<grid, 128, SMEM_TOTAL>>>(scales, bias, qweight, qzeros, out);
}